// round 2
// baseline (speedup 1.0000x reference)
#include <cuda_runtime.h>
#include <math.h>

#define HH 512
#define WW 512
#define NMAPS 160      // 32 * 5
#define STRIPS 4
#define RPS (HH/STRIPS)
#define NTH 512

// Partial top-3 per (map, strip) — tiny scratch, allocation-free.
__device__ float g_pval[NMAPS * STRIPS * 3];
__device__ int   g_pidx[NMAPS * STRIPS * 3];

__device__ __forceinline__ bool better(float av, int ai, float bv, int bi) {
    // lax.top_k ordering: value desc, index asc among ties
    return (av > bv) || ((av == bv) && (ai < bi));
}

// One block = one (map, row-strip). One thread per column.
// Separable 5x5 max: horizontal 5-max via a double-buffered shared row
// (+/-2 halo), vertical 5-max via per-thread register ring (column is
// thread-private). One __syncthreads per row.
__global__ void __launch_bounds__(NTH) nms_topk_kernel(const float* __restrict__ hm) {
    const int map   = blockIdx.x / STRIPS;
    const int strip = blockIdx.x % STRIPS;
    const int c     = threadIdx.x;
    const float* base = hm + (long long)map * HH * WW;
    const int r0 = strip * RPS, r1 = r0 + RPS - 1;

    __shared__ float raw[2][WW + 4];  // double-buffered padded rows; halos = -inf
    __shared__ float sv[NTH * 3];
    __shared__ int   si[NTH * 3];

    if (c < 2) {
        raw[0][c] = -INFINITY; raw[0][WW + 2 + c] = -INFINITY;
        raw[1][c] = -INFINITY; raw[1][WW + 2 + c] = -INFINITY;
    }

    // Register rings: rm* = row-max of rows lr-4..lr ; ra* = raw value rows lr-4..lr (this column)
    float rm0 = -INFINITY, rm1 = -INFINITY, rm2 = -INFINITY, rm3 = -INFINITY, rm4 = -INFINITY;
    float ra0 = 0.f, ra1 = 0.f, ra2 = 0.f, ra3 = 0.f, ra4 = 0.f;

    // Thread-local top-3 (sorted desc; strict > keeps earliest index on ties)
    float v0 = -INFINITY, v1 = -INFINITY, v2 = -INFINITY;
    int   i0 = 0, i1 = 0, i2 = 0;

    const int lr0 = r0 - 2;
    float nxt = (lr0 >= 0 && lr0 < HH) ? base[lr0 * WW + c] : 0.0f;

    for (int lr = lr0; lr <= r1 + 2; ++lr) {
        float cur = nxt;
        int nl = lr + 1;
        if (nl >= 0 && nl < HH && nl <= r1 + 2) nxt = base[nl * WW + c];  // prefetch next row

        const int pb = lr & 1;
        bool inr = (lr >= 0 && lr < HH);
        if (inr) raw[pb][c + 2] = cur;
        __syncthreads();   // single barrier: next iter writes the other buffer

        float rm = -INFINITY;
        if (inr) {
            rm = fmaxf(fmaxf(raw[pb][c], raw[pb][c + 1]), fmaxf(raw[pb][c + 3], raw[pb][c + 4]));
            rm = fmaxf(rm, cur);
        }

        // rotate rings
        rm0 = rm1; rm1 = rm2; rm2 = rm3; rm3 = rm4; rm4 = rm;
        ra0 = ra1; ra1 = ra2; ra2 = ra3; ra3 = ra4; ra4 = cur;

        int er = lr - 2;   // row being evaluated (rows er-2..er+2 live in rm ring)
        if (er >= r0 && er <= r1) {
            float center = ra2;
            float vm = fmaxf(fmaxf(fmaxf(rm0, rm1), fmaxf(rm2, rm3)), rm4);
            float v = (center == vm) ? center : 0.0f;   // == reference hm * (hm == pool)
            int idx = er * WW + c;
            if (v > v0)      { v2=v1; i2=i1; v1=v0; i1=i0; v0=v; i0=idx; }
            else if (v > v1) { v2=v1; i2=i1; v1=v;  i1=idx; }
            else if (v > v2) { v2=v;  i2=idx; }
        }
    }

    // Block-wide top-3 merge (sorted-triple tree reduction)
    const int t = c;
    sv[t*3+0] = v0; sv[t*3+1] = v1; sv[t*3+2] = v2;
    si[t*3+0] = i0; si[t*3+1] = i1; si[t*3+2] = i2;
    __syncthreads();
    for (int s = NTH / 2; s > 0; s >>= 1) {
        if (t < s) {
            float av[3], bv[3], ov[3]; int ai[3], bi[3], oi[3];
            #pragma unroll
            for (int k = 0; k < 3; k++) {
                av[k] = sv[t*3+k];       ai[k] = si[t*3+k];
                bv[k] = sv[(t+s)*3+k];   bi[k] = si[(t+s)*3+k];
            }
            int pa = 0, pbm = 0;
            #pragma unroll
            for (int k = 0; k < 3; k++) {   // merge two sorted triples -> top 3
                if (better(av[pa], ai[pa], bv[pbm], bi[pbm])) { ov[k]=av[pa]; oi[k]=ai[pa]; pa++; }
                else                                          { ov[k]=bv[pbm]; oi[k]=bi[pbm]; pbm++; }
            }
            #pragma unroll
            for (int k = 0; k < 3; k++) { sv[t*3+k] = ov[k]; si[t*3+k] = oi[k]; }
        }
        __syncthreads();
    }
    if (t == 0) {
        int pb2 = blockIdx.x * 3;
        #pragma unroll
        for (int k = 0; k < 3; k++) { g_pval[pb2 + k] = sv[k]; g_pidx[pb2 + k] = si[k]; }
    }
}

// Merge strip partials per map, softmax, pack outputs:
// out[0:960)      coords (bs,nc,3,2) as float
// out[960:1440)   scores (bs,nc,3)
// out[1440:1920)  indices (bs,nc,3) as float
__global__ void finalize_kernel(float* __restrict__ out) {
    int m = threadIdx.x + blockIdx.x * blockDim.x;
    if (m >= NMAPS) return;
    float bv0 = -INFINITY, bv1 = -INFINITY, bv2 = -INFINITY;
    int   bi0 = 0, bi1 = 0, bi2 = 0;
    for (int s = 0; s < STRIPS; s++) {
        int pb = (m * STRIPS + s) * 3;
        #pragma unroll
        for (int k = 0; k < 3; k++) {
            float v = g_pval[pb + k]; int i = g_pidx[pb + k];
            if (better(v, i, bv0, bi0))      { bv2=bv1; bi2=bi1; bv1=bv0; bi1=bi0; bv0=v; bi0=i; }
            else if (better(v, i, bv1, bi1)) { bv2=bv1; bi2=bi1; bv1=v; bi1=i; }
            else if (better(v, i, bv2, bi2)) { bv2=v; bi2=i; }
        }
    }
    float e0 = 1.0f;                 // expf(bv0 - bv0)
    float e1 = expf(bv1 - bv0);
    float e2 = expf(bv2 - bv0);
    float inv = 1.0f / (e0 + e1 + e2);

    float* oc = out + m * 6;
    oc[0] = (float)(bi0 / WW); oc[1] = (float)(bi0 % WW);
    oc[2] = (float)(bi1 / WW); oc[3] = (float)(bi1 % WW);
    oc[4] = (float)(bi2 / WW); oc[5] = (float)(bi2 % WW);

    float* os = out + NMAPS * 6 + m * 3;
    os[0] = e0 * inv; os[1] = e1 * inv; os[2] = e2 * inv;

    float* oi = out + NMAPS * 9 + m * 3;
    oi[0] = (float)bi0; oi[1] = (float)bi1; oi[2] = (float)bi2;
}

extern "C" void kernel_launch(void* const* d_in, const int* in_sizes, int n_in,
                              void* d_out, int out_size) {
    const float* hm = (const float*)d_in[0];
    float* out = (float*)d_out;
    nms_topk_kernel<<<NMAPS * STRIPS, NTH>>>(hm);
    finalize_kernel<<<1, 192>>>(out);
}

// round 7
// speedup vs baseline: 1.3677x; 1.3677x over previous
#include <cuda_runtime.h>
#include <math.h>

#define HH 512
#define WW 512
#define NMAPS 160          // 32 * 5
#define STRIPS 4
#define RPS (HH / STRIPS)  // 128
#define NTH 256            // threads per block; each thread owns 2 columns
#define RB 4               // rows per batch
#define NGROUPS ((RPS + 4) / RB)   // 33 (rows r0-2 .. r1+2 inclusive)
#define STRIDE (WW + 4)    // padded shared row (floats), float2-aligned

// Partial top-3 per (map, strip) + completion counter (self-resetting).
__device__ float g_pval[NMAPS * STRIPS * 3];
__device__ int   g_pidx[NMAPS * STRIPS * 3];
__device__ int   g_ctr = 0;

__device__ __forceinline__ bool better(float av, int ai, float bv, int bi) {
    // lax.top_k ordering: value desc, index asc among ties
    return (av > bv) || ((av == bv) && (ai < bi));
}

__device__ __forceinline__ void insert3(float v, int idx,
                                        float& v0, float& v1, float& v2,
                                        int& i0, int& i1, int& i2) {
    if (v > v0)      { v2=v1; i2=i1; v1=v0; i1=i0; v0=v; i0=idx; }
    else if (v > v1) { v2=v1; i2=i1; v1=v;  i1=idx; }
    else if (v > v2) { v2=v;  i2=idx; }
}

// One block = one (map, row-strip). 256 threads, 2 columns/thread.
// Separable 5x5 max: horizontal via double-buffered shared rows (4/batch),
// vertical via per-thread register rings fed from the staged shared data.
// ONE __syncthreads per 4-row group.
__global__ void __launch_bounds__(NTH, 5) nms_topk_kernel(const float* __restrict__ hm,
                                                          float* __restrict__ out) {
    const int map   = blockIdx.x / STRIPS;
    const int strip = blockIdx.x % STRIPS;
    const int t     = threadIdx.x;
    const int c0    = 2 * t;            // first of this thread's two columns
    const float* base = hm + (long long)map * HH * WW;
    const int r0 = strip * RPS, r1 = r0 + RPS - 1;
    const int lr0 = r0 - 2;

    // Shared: row buffers; after mainloop the same storage is reused for merge.
    __shared__ __align__(16) float buf[2 * RB * STRIDE];   // 16.1 KB
    float* sv = buf;                          // [NTH*3] merge values (aliased)
    int*   si = (int*)(buf + NTH * 3);        // [NTH*3] merge indices (aliased)

    // Halo init (-inf) for all 8 staged rows, written once.
    if (t < 2 * RB) {
        buf[t * STRIDE + 0] = -INFINITY;
        buf[t * STRIDE + 1] = -INFINITY;
        buf[t * STRIDE + WW + 2] = -INFINITY;
        buf[t * STRIDE + WW + 3] = -INFINITY;
    }

    // rm rings (depth 5): horizontal row-max for rows lr-4..lr, per column.
    float rmA[5], rmB[5];
    // ra rings (depth 3): raw center values; AFTER rotation ra[0] = row lr-2.
    float raA[3], raB[3];
    #pragma unroll
    for (int k = 0; k < 5; k++) { rmA[k] = -INFINITY; rmB[k] = -INFINITY; }
    #pragma unroll
    for (int k = 0; k < 3; k++) { raA[k] = 0.f; raB[k] = 0.f; }

    float v0 = -INFINITY, v1 = -INFINITY, v2 = -INFINITY;
    int   i0 = 0, i1 = 0, i2 = 0;

    // Prolog: load + stage group 0 into buf[0].
    {
        float2 nv[RB];
        #pragma unroll
        for (int j = 0; j < RB; j++) {
            int lr = lr0 + j;
            if (lr >= 0 && lr < HH) nv[j] = ((const float2*)(base + lr * WW))[t];
        }
        #pragma unroll
        for (int j = 0; j < RB; j++) {
            int lr = lr0 + j;
            if (lr >= 0 && lr < HH)
                ((float2*)(buf + j * STRIDE + 2))[t] = nv[j];
        }
    }
    __syncthreads();

    for (int g = 0; g < NGROUPS; g++) {
        const int lrg = lr0 + g * RB;

        // Issue next group's loads first (DRAM latency hidden by this group's compute).
        float2 nv[RB];
        const bool more = (g + 1 < NGROUPS);
        if (more) {
            #pragma unroll
            for (int j = 0; j < RB; j++) {
                int lr = lrg + RB + j;
                if (lr >= 0 && lr < HH) nv[j] = ((const float2*)(base + lr * WW))[t];
            }
        }

        // Process current group from buf[g&1].
        const float* bb = buf + (g & 1) * (RB * STRIDE);
        #pragma unroll
        for (int j = 0; j < RB; j++) {
            const int lr = lrg + j;
            float hA = -INFINITY, hB = -INFINITY, cA = 0.f, cB = 0.f;
            if (lr >= 0 && lr < HH) {
                const float2* p2 = (const float2*)(bb + j * STRIDE);
                float2 x0 = p2[t], x1 = p2[t + 1], x2 = p2[t + 2];  // cols c0-2..c0+3
                hA = fmaxf(fmaxf(fmaxf(x0.x, x0.y), fmaxf(x1.x, x1.y)), x2.x);
                hB = fmaxf(fmaxf(fmaxf(x0.y, x1.x), fmaxf(x1.y, x2.x)), x2.y);
                cA = x1.x; cB = x1.y;   // this thread's raw center values, row lr
            }
            // rotate rings FIRST, then read centers (ra[0] == row lr-2 == er).
            rmA[0]=rmA[1]; rmA[1]=rmA[2]; rmA[2]=rmA[3]; rmA[3]=rmA[4]; rmA[4]=hA;
            rmB[0]=rmB[1]; rmB[1]=rmB[2]; rmB[2]=rmB[3]; rmB[3]=rmB[4]; rmB[4]=hB;
            raA[0]=raA[1]; raA[1]=raA[2]; raA[2]=cA;
            raB[0]=raB[1]; raB[1]=raB[2]; raB[2]=cB;
            float eA = raA[0], eB = raB[0];          // center values of row lr-2

            const int er = lr - 2;
            if (er >= r0 && er <= r1) {
                float vmA = fmaxf(fmaxf(fmaxf(rmA[0], rmA[1]), fmaxf(rmA[2], rmA[3])), rmA[4]);
                float vmB = fmaxf(fmaxf(fmaxf(rmB[0], rmB[1]), fmaxf(rmB[2], rmB[3])), rmB[4]);
                float vA = (eA == vmA) ? eA : 0.0f;   // hm * (hm == pool)
                float vB = (eB == vmB) ? eB : 0.0f;
                int idx = er * WW + c0;
                insert3(vA, idx,     v0, v1, v2, i0, i1, i2);
                insert3(vB, idx + 1, v0, v1, v2, i0, i1, i2);
            }
        }

        // Stage next group into the other buffer (its readers finished at the
        // previous barrier), then one barrier covers both hazards.
        if (more) {
            float* nb = buf + ((g + 1) & 1) * (RB * STRIDE);
            #pragma unroll
            for (int j = 0; j < RB; j++) {
                int lr = lrg + RB + j;
                if (lr >= 0 && lr < HH)
                    ((float2*)(nb + j * STRIDE + 2))[t] = nv[j];
            }
        }
        __syncthreads();
    }

    // ---- Block-wide top-3 merge (sorted-triple tree reduction, aliased smem) ----
    sv[t*3+0] = v0; sv[t*3+1] = v1; sv[t*3+2] = v2;
    si[t*3+0] = i0; si[t*3+1] = i1; si[t*3+2] = i2;
    __syncthreads();
    for (int s = NTH / 2; s > 0; s >>= 1) {
        if (t < s) {
            float av[3], bv[3], ov[3]; int ai[3], bi[3], oi[3];
            #pragma unroll
            for (int k = 0; k < 3; k++) {
                av[k] = sv[t*3+k];       ai[k] = si[t*3+k];
                bv[k] = sv[(t+s)*3+k];   bi[k] = si[(t+s)*3+k];
            }
            int pa = 0, pb = 0;
            #pragma unroll
            for (int k = 0; k < 3; k++) {
                if (better(av[pa], ai[pa], bv[pb], bi[pb])) { ov[k]=av[pa]; oi[k]=ai[pa]; pa++; }
                else                                        { ov[k]=bv[pb]; oi[k]=bi[pb]; pb++; }
            }
            #pragma unroll
            for (int k = 0; k < 3; k++) { sv[t*3+k] = ov[k]; si[t*3+k] = oi[k]; }
        }
        __syncthreads();
    }

    __shared__ int s_last;
    if (t == 0) {
        int pb2 = blockIdx.x * 3;
        #pragma unroll
        for (int k = 0; k < 3; k++) { g_pval[pb2 + k] = sv[k]; g_pidx[pb2 + k] = si[k]; }
        __threadfence();
        int old = atomicAdd(&g_ctr, 1);
        s_last = (old == gridDim.x - 1) ? 1 : 0;
    }
    __syncthreads();

    // ---- Last block finalizes: merge strips, softmax, pack outputs ----
    // out[0:960) coords (bs,nc,3,2) | [960:1440) scores | [1440:1920) indices
    if (s_last) {
        int m = t;
        if (m < NMAPS) {
            float bv0 = -INFINITY, bv1 = -INFINITY, bv2 = -INFINITY;
            int   bi0 = 0, bi1 = 0, bi2 = 0;
            for (int s = 0; s < STRIPS; s++) {
                int pb = (m * STRIPS + s) * 3;
                #pragma unroll
                for (int k = 0; k < 3; k++) {
                    float v = __ldcg(&g_pval[pb + k]);
                    int   i = __ldcg(&g_pidx[pb + k]);
                    if (better(v, i, bv0, bi0))      { bv2=bv1; bi2=bi1; bv1=bv0; bi1=bi0; bv0=v; bi0=i; }
                    else if (better(v, i, bv1, bi1)) { bv2=bv1; bi2=bi1; bv1=v; bi1=i; }
                    else if (better(v, i, bv2, bi2)) { bv2=v; bi2=i; }
                }
            }
            float e1 = expf(bv1 - bv0);
            float e2 = expf(bv2 - bv0);
            float inv = 1.0f / (1.0f + e1 + e2);

            float* oc = out + m * 6;
            oc[0] = (float)(bi0 / WW); oc[1] = (float)(bi0 % WW);
            oc[2] = (float)(bi1 / WW); oc[3] = (float)(bi1 % WW);
            oc[4] = (float)(bi2 / WW); oc[5] = (float)(bi2 % WW);

            float* os = out + NMAPS * 6 + m * 3;
            os[0] = inv; os[1] = e1 * inv; os[2] = e2 * inv;

            float* oi = out + NMAPS * 9 + m * 3;
            oi[0] = (float)bi0; oi[1] = (float)bi1; oi[2] = (float)bi2;
        }
        if (t == 0) g_ctr = 0;   // self-reset for graph replay
    }
}

extern "C" void kernel_launch(void* const* d_in, const int* in_sizes, int n_in,
                              void* d_out, int out_size) {
    const float* hm = (const float*)d_in[0];
    float* out = (float*)d_out;
    nms_topk_kernel<<<NMAPS * STRIPS, NTH>>>(hm, out);
}

// round 8
// speedup vs baseline: 1.6222x; 1.1861x over previous
#include <cuda_runtime.h>
#include <math.h>

#define HH 512
#define WW 512
#define NMAPS 160          // 32 * 5
#define STRIPS 4
#define RPS (HH / STRIPS)  // 128 rows per strip
#define NTH 128            // threads per block; each thread owns 4 columns
#define NEG_INF (-INFINITY)

// Partial top-3 per (map, strip) + completion counter (self-resetting).
__device__ float g_pval[NMAPS * STRIPS * 3];
__device__ int   g_pidx[NMAPS * STRIPS * 3];
__device__ int   g_ctr = 0;

__device__ __forceinline__ bool better(float av, int ai, float bv, int bi) {
    // lax.top_k ordering: value desc, index asc among ties
    return (av > bv) || ((av == bv) && (ai < bi));
}

// One block = one (map, row-strip). 128 threads = 4 warps; warp w owns columns
// [128w, 128w+128). Thread owns 4 columns (float4). Horizontal 5-max halo via
// warp shuffles; warp-edge lanes read a 2-col halo directly (L1-hot).
// Vertical 5-max via pair-max recurrence in registers. NO smem / barriers in
// the mainloop.
__global__ void __launch_bounds__(NTH, 6) nms_topk_kernel(const float* __restrict__ hm,
                                                          float* __restrict__ out) {
    const int map   = blockIdx.x / STRIPS;
    const int strip = blockIdx.x % STRIPS;
    const int t     = threadIdx.x;
    const int lane  = t & 31;
    const int wb    = (t >> 5) * 128;   // warp's first column
    const int c0    = 4 * t;            // this thread's first column
    const float* base = hm + (long long)map * HH * WW;
    const int r0 = strip * RPS, r1 = r0 + RPS - 1;

    // Vertical state per column (x..w = cols c0..c0+3):
    //   hp = h of previous row; q1 = max(h[-1],h[-2]); q2 = max(h[-2],h[-3]);
    //   q3 = max(h[-3],h[-4]).  vm(row) = max(q3, q1, h)   (5-row window)
    float4 q1, q2, q3, hp;
    q1 = q2 = q3 = hp = make_float4(NEG_INF, NEG_INF, NEG_INF, NEG_INF);
    // Raw-value delay line: d2 = row lr-2 (center), d1 = row lr-1.
    float4 d1 = make_float4(0.f,0.f,0.f,0.f), d2 = d1;

    // Thread-local top-3 (sorted desc).
    float vt0 = NEG_INF, vt1 = NEG_INF, vt2 = NEG_INF;
    int   it0 = 0, it1 = 0, it2 = 0;

    // Row loader: clamped row, own float4 + warp-edge halo float2.
    auto ldrow = [&](int lr, float4& f, float2& hx) {
        int rc = min(max(lr, 0), HH - 1);
        const float* p = base + rc * WW;
        f = *(const float4*)(p + c0);
        if (lane == 0)
            hx = (wb > 0) ? *(const float2*)(p + wb - 2)
                          : make_float2(NEG_INF, NEG_INF);
        else if (lane == 31)
            hx = (wb + 128 < WW) ? *(const float2*)(p + wb + 128)
                                 : make_float2(NEG_INF, NEG_INF);
    };

    int ib = r0 * WW + c0;   // flat index of (er, c0), maintained incrementally

    auto ins = [&](float v, int idx) {
        if (v > vt2) {                       // rare path; strict > keeps ties stable
            if (v > vt0)      { vt2=vt1; it2=it1; vt1=vt0; it1=it0; vt0=v; it0=idx; }
            else if (v > vt1) { vt2=vt1; it2=it1; vt1=v;  it1=idx; }
            else              { vt2=v;  it2=idx; }
        }
    };

    // Process one loaded row lr; when do_ins, emit candidates for er = lr-2.
    auto process = [&](float4 x, float2 hx, int lr, bool do_ins) {
        float lm2 = __shfl_up_sync(0xffffffffu, x.z, 1);   // col c0-2
        float lm1 = __shfl_up_sync(0xffffffffu, x.w, 1);   // col c0-1
        float rp0 = __shfl_down_sync(0xffffffffu, x.x, 1); // col c0+4
        float rp1 = __shfl_down_sync(0xffffffffu, x.y, 1); // col c0+5
        if (lane == 0)  { lm2 = hx.x; lm1 = hx.y; }
        if (lane == 31) { rp0 = hx.x; rp1 = hx.y; }

        float a  = fmaxf(x.y, x.z);
        float h0 = fmaxf(fmaxf(lm2, lm1), fmaxf(x.x, a));
        float h1 = fmaxf(fmaxf(lm1, x.x), fmaxf(a, x.w));
        float h2 = fmaxf(fmaxf(x.x, a),  fmaxf(x.w, rp0));
        float h3 = fmaxf(fmaxf(a, x.w),  fmaxf(rp0, rp1));
        if ((unsigned)lr >= (unsigned)HH) { h0 = h1 = h2 = h3 = NEG_INF; }

        if (do_ins) {
            float vm0 = fmaxf(q3.x, fmaxf(q1.x, h0));
            float vm1 = fmaxf(q3.y, fmaxf(q1.y, h1));
            float vm2 = fmaxf(q3.z, fmaxf(q1.z, h2));
            float vm3 = fmaxf(q3.w, fmaxf(q1.w, h3));
            float v0c = (d2.x == vm0) ? d2.x : 0.0f;   // hm * (hm == pool)
            float v1c = (d2.y == vm1) ? d2.y : 0.0f;
            float v2c = (d2.z == vm2) ? d2.z : 0.0f;
            float v3c = (d2.w == vm3) ? d2.w : 0.0f;
            ins(v0c, ib);
            ins(v1c, ib + 1);
            ins(v2c, ib + 2);
            ins(v3c, ib + 3);
        }

        // Rotate state (uses above read pre-rotation values).
        q3 = q2; q2 = q1;
        q1 = make_float4(fmaxf(h0, hp.x), fmaxf(h1, hp.y),
                         fmaxf(h2, hp.z), fmaxf(h3, hp.w));
        hp = make_float4(h0, h1, h2, h3);
        d2 = d1; d1 = x;
    };

    // ---- Warm-up: rows r0-2 .. r0+1 fill the rings (no candidates) ----
    {
        float4 w0, w1, w2, w3; float2 e0, e1, e2, e3;
        ldrow(r0 - 2, w0, e0); ldrow(r0 - 1, w1, e1);
        ldrow(r0,     w2, e2); ldrow(r0 + 1, w3, e3);
        process(w0, e0, r0 - 2, false);
        process(w1, e1, r0 - 1, false);
        process(w2, e2, r0,     false);
        process(w3, e3, r0 + 1, false);
    }

    // ---- Main: rows r0+2 .. r1+2 (128 rows), prefetch distance 2 ----
    float4 f0, f1; float2 g0, g1;
    ldrow(r0 + 2, f0, g0);
    ldrow(r0 + 3, f1, g1);
    int lr = r0 + 2;
    for (int it = 0; it < 16; it++) {
        #pragma unroll
        for (int j = 0; j < 8; j++) {
            float4 x = f0; float2 hx = g0;
            f0 = f1; g0 = g1;
            ldrow(lr + 2, f1, g1);        // clamped; tail reloads row 511, harmless
            process(x, hx, lr, true);
            ib += WW;
            lr++;
        }
    }

    // ---- Block-wide top-3 merge (sorted-triple tree reduction) ----
    __shared__ float sv[NTH * 3];
    __shared__ int   si[NTH * 3];
    sv[t*3+0] = vt0; sv[t*3+1] = vt1; sv[t*3+2] = vt2;
    si[t*3+0] = it0; si[t*3+1] = it1; si[t*3+2] = it2;
    __syncthreads();
    for (int s = NTH / 2; s > 0; s >>= 1) {
        if (t < s) {
            float av[3], bv[3], ov[3]; int ai[3], bi[3], oi[3];
            #pragma unroll
            for (int k = 0; k < 3; k++) {
                av[k] = sv[t*3+k];       ai[k] = si[t*3+k];
                bv[k] = sv[(t+s)*3+k];   bi[k] = si[(t+s)*3+k];
            }
            int pa = 0, pb = 0;
            #pragma unroll
            for (int k = 0; k < 3; k++) {
                if (better(av[pa], ai[pa], bv[pb], bi[pb])) { ov[k]=av[pa]; oi[k]=ai[pa]; pa++; }
                else                                        { ov[k]=bv[pb]; oi[k]=bi[pb]; pb++; }
            }
            #pragma unroll
            for (int k = 0; k < 3; k++) { sv[t*3+k] = ov[k]; si[t*3+k] = oi[k]; }
        }
        __syncthreads();
    }

    __shared__ int s_last;
    if (t == 0) {
        int pb2 = blockIdx.x * 3;
        #pragma unroll
        for (int k = 0; k < 3; k++) { g_pval[pb2 + k] = sv[k]; g_pidx[pb2 + k] = si[k]; }
        __threadfence();
        int old = atomicAdd(&g_ctr, 1);
        s_last = (old == gridDim.x - 1) ? 1 : 0;
    }
    __syncthreads();

    // ---- Last block finalizes: merge strips, softmax, pack outputs ----
    // out[0:960) coords (bs,nc,3,2) | [960:1440) scores | [1440:1920) indices
    if (s_last) {
        for (int m = t; m < NMAPS; m += NTH) {
            float bv0 = NEG_INF, bv1 = NEG_INF, bv2 = NEG_INF;
            int   bi0 = 0, bi1 = 0, bi2 = 0;
            for (int s = 0; s < STRIPS; s++) {
                int pb = (m * STRIPS + s) * 3;
                #pragma unroll
                for (int k = 0; k < 3; k++) {
                    float v = __ldcg(&g_pval[pb + k]);
                    int   i = __ldcg(&g_pidx[pb + k]);
                    if (better(v, i, bv0, bi0))      { bv2=bv1; bi2=bi1; bv1=bv0; bi1=bi0; bv0=v; bi0=i; }
                    else if (better(v, i, bv1, bi1)) { bv2=bv1; bi2=bi1; bv1=v; bi1=i; }
                    else if (better(v, i, bv2, bi2)) { bv2=v; bi2=i; }
                }
            }
            float e1 = expf(bv1 - bv0);
            float e2 = expf(bv2 - bv0);
            float inv = 1.0f / (1.0f + e1 + e2);

            float* oc = out + m * 6;
            oc[0] = (float)(bi0 / WW); oc[1] = (float)(bi0 % WW);
            oc[2] = (float)(bi1 / WW); oc[3] = (float)(bi1 % WW);
            oc[4] = (float)(bi2 / WW); oc[5] = (float)(bi2 % WW);

            float* os = out + NMAPS * 6 + m * 3;
            os[0] = inv; os[1] = e1 * inv; os[2] = e2 * inv;

            float* oi = out + NMAPS * 9 + m * 3;
            oi[0] = (float)bi0; oi[1] = (float)bi1; oi[2] = (float)bi2;
        }
        if (t == 0) g_ctr = 0;   // self-reset for graph replay
    }
}

extern "C" void kernel_launch(void* const* d_in, const int* in_sizes, int n_in,
                              void* d_out, int out_size) {
    const float* hm = (const float*)d_in[0];
    float* out = (float*)d_out;
    nms_topk_kernel<<<NMAPS * STRIPS, NTH>>>(hm, out);
}